// round 13
// baseline (speedup 1.0000x reference)
#include <cuda_runtime.h>
#include <cuda_bf16.h>
#include <stdint.h>

// BiLSTM B=128,S=1024,D=128,H=256 — bf16 3-split HMMA, warp-specialized.
// 128 CTAs = dir(2) x rowslice(8, M=128) x btile(8, N=16). 640 threads:
// 16 compute warps (GEMM + z reduce, R11 layout) + 4 state warps (gates,
// publish, flag poll, h-slice copy, outputs). Named-barrier handshake:
//  bar1: h tiles ready   (state -> compute)
//  bar2: z reduce        (compute internal, 512)
//  bar3: z ready         (compute -> state)
//  bar4: h tiles consumed(compute -> state)

#define S_LEN 1024
#define NTHR  640

#define A_HI_OFF 0          // 8 strips x 24kt x 512B
#define A_LO_OFF 98304
#define B_HI_OFF 196608     // 48 tiles x 128B (x 4KB | h 8KB)
#define B_LO_OFF 208896
#define Z_OFF    221184     // float z[128][16] = 8KB
#define SMEM_BYTES 229376

__device__ unsigned char g_hx[2][2][8][8][2048]; // [parity][dir][btl][rs][hi1K|lo1K]
__device__ unsigned g_flag[128];                 // cumulative warp arrivals (+4/step)

__global__ void reset_flag_kernel() {
    if (threadIdx.x < 128) g_flag[threadIdx.x] = 0u;
}

__device__ __forceinline__ uint32_t smem_u32(const void* p) {
    uint32_t a;
    asm("{ .reg .u64 t; cvta.to.shared.u64 t, %1; cvt.u32.u64 %0, t; }"
        : "=r"(a) : "l"(p));
    return a;
}
__device__ __forceinline__ unsigned ld_acquire_gpu(const unsigned* p) {
    unsigned v;
    asm volatile("ld.acquire.gpu.global.u32 %0, [%1];" : "=r"(v) : "l"(p) : "memory");
    return v;
}
__device__ __forceinline__ void red_release_gpu(unsigned* p, unsigned v) {
    asm volatile("red.release.gpu.global.add.u32 [%0], %1;" :: "l"(p), "r"(v) : "memory");
}
__device__ __forceinline__ void bar_sync_n(int id, int cnt) {
    asm volatile("bar.sync %0, %1;" :: "r"(id), "r"(cnt) : "memory");
}
__device__ __forceinline__ void bar_arrive_n(int id, int cnt) {
    asm volatile("bar.arrive %0, %1;" :: "r"(id), "r"(cnt) : "memory");
}
__device__ __forceinline__ void ldsm4(uint32_t* r, uint32_t a) {
    asm volatile("ldmatrix.sync.aligned.m8n8.x4.shared.b16 {%0,%1,%2,%3}, [%4];"
                 : "=r"(r[0]), "=r"(r[1]), "=r"(r[2]), "=r"(r[3]) : "r"(a));
}
__device__ __forceinline__ void ldsm4t(uint32_t* r, uint32_t a) {
    asm volatile("ldmatrix.sync.aligned.m8n8.x4.trans.shared.b16 {%0,%1,%2,%3}, [%4];"
                 : "=r"(r[0]), "=r"(r[1]), "=r"(r[2]), "=r"(r[3]) : "r"(a));
}
__device__ __forceinline__ void mma16816(float* d, const uint32_t* a, const uint32_t* b) {
    asm volatile(
        "mma.sync.aligned.m16n8k16.row.col.f32.bf16.bf16.f32 "
        "{%0,%1,%2,%3}, {%4,%5,%6,%7}, {%8,%9}, {%0,%1,%2,%3};"
        : "+f"(d[0]), "+f"(d[1]), "+f"(d[2]), "+f"(d[3])
        : "r"(a[0]), "r"(a[1]), "r"(a[2]), "r"(a[3]), "r"(b[0]), "r"(b[1]));
}

__device__ __forceinline__ uint2 split_pack4(float4 v, uint2& lo_out) {
    __nv_bfloat16 h0 = __float2bfloat16_rn(v.x), h1 = __float2bfloat16_rn(v.y);
    __nv_bfloat16 h2 = __float2bfloat16_rn(v.z), h3 = __float2bfloat16_rn(v.w);
    __nv_bfloat16 l0 = __float2bfloat16_rn(v.x - __bfloat162float(h0));
    __nv_bfloat16 l1 = __float2bfloat16_rn(v.y - __bfloat162float(h1));
    __nv_bfloat16 l2 = __float2bfloat16_rn(v.z - __bfloat162float(h2));
    __nv_bfloat16 l3 = __float2bfloat16_rn(v.w - __bfloat162float(h3));
    uint2 hi;
    hi.x = ((uint32_t)__bfloat16_as_ushort(h1) << 16) | __bfloat16_as_ushort(h0);
    hi.y = ((uint32_t)__bfloat16_as_ushort(h3) << 16) | __bfloat16_as_ushort(h2);
    lo_out.x = ((uint32_t)__bfloat16_as_ushort(l1) << 16) | __bfloat16_as_ushort(l0);
    lo_out.y = ((uint32_t)__bfloat16_as_ushort(l3) << 16) | __bfloat16_as_ushort(l2);
    return hi;
}
__device__ __forceinline__ float sigmoidf_fast(float x) {
    return 1.0f / (1.0f + __expf(-x));
}
__device__ __forceinline__ float tanhf_fast(float x) {
    return 1.0f - 2.0f / (1.0f + __expf(2.0f * x));
}

__global__ void __launch_bounds__(NTHR, 1)
bilstm_mma_kernel(const float* __restrict__ x,
                  const float* __restrict__ Wf, const float* __restrict__ bf,
                  const float* __restrict__ Wb, const float* __restrict__ bb,
                  float* __restrict__ out)
{
    extern __shared__ char smem[];
    const uint32_t sb = smem_u32(smem);
    const int tid  = threadIdx.x;
    const int wid  = tid >> 5;
    const int lane = tid & 31;

    const int dir = blockIdx.x >> 6;
    const int rs  = (blockIdx.x >> 3) & 7;
    const int btl = blockIdx.x & 7;
    const int b_base = btl * 16;

    const float* W   = dir ? Wb : Wf;    // (4,256,384)
    const float* bia = dir ? bb : bf;
    float* z_s = (float*)(smem + Z_OFF);

    // zero h-region tiles (s=0 state)
    for (int i = tid; i < 1024; i += NTHR) {
        int buf = i >> 9, r = i & 511;
        ((uint4*)(smem + (buf ? B_LO_OFF : B_HI_OFF) + 4096))[r] = make_uint4(0, 0, 0, 0);
    }
    // weights -> bf16 hi/lo ldmatrix tiles
    for (int idx = tid; idx < 128 * 96; idx += NTHR) {
        int r = idx / 96, j = idx % 96, k0 = j * 4;
        int wr = (r >> 5) * 256 + rs * 32 + (r & 31);
        float4 v = *(const float4*)(W + (size_t)wr * 384 + k0);
        uint2 lo, hi = split_pack4(v, lo);
        uint32_t byte = (uint32_t)(((r >> 4) * 24 + (k0 >> 4)) * 512
                       + (((k0 >> 3) & 1) * 2 + ((r >> 3) & 1)) * 128
                       + (r & 7) * 16 + (k0 & 7) * 2);
        *(uint2*)(smem + A_HI_OFF + byte) = hi;
        *(uint2*)(smem + A_LO_OFF + byte) = lo;
    }
    // x(0) fill (compute threads only: tid < 512)
    const int xk = tid >> 2, xj = tid & 3;
    const uint32_t xfill_off = (uint32_t)(((xk >> 3) * 2 + (xj >> 1)) * 128
                             + (xk & 7) * 16 + (xj & 1) * 8);
    if (tid < 512) {
        const int t0 = dir ? (S_LEN - 1) : 0;
        float4 v = __ldg((const float4*)(x + (size_t)xk * (S_LEN * 128)
                                           + (size_t)t0 * 128 + b_base + xj * 4));
        uint2 lo, hi = split_pack4(v, lo);
        *(uint2*)(smem + B_HI_OFF + xfill_off) = hi;
        *(uint2*)(smem + B_LO_OFF + xfill_off) = lo;
    }
    __syncthreads();

    if (wid < 16) {
        // ================= COMPUTE WARPS =================
        const int wlow  = wid & 7;
        const int whalf = wid >> 3;
        const uint32_t aBase = sb + A_HI_OFF + (uint32_t)(wlow * 24 * 512)
                             + ((lane >> 3) * 128) + ((lane & 7) * 16);
        const int sub = lane >> 3;
        const uint32_t bBase = sb + B_HI_OFF
                             + (uint32_t)((((sub & 1) * 2) + (sub >> 1)) * 128)
                             + ((lane & 7) * 16);
        const int r1 = wlow * 16 + (lane >> 2);
        const int r2 = r1 + 8;
        const int n0 = (lane & 3) * 2;

        for (int s = 0; s < S_LEN; ++s) {
            float a0e[4] = {0,0,0,0}, a0o[4] = {0,0,0,0};
            float a1e[4] = {0,0,0,0}, a1o[4] = {0,0,0,0};

            // C1: x-part GEMM, 4 kts
            {
                int kt = whalf;
#pragma unroll
                for (int i = 0; i < 4; ++i, kt += 2) {
                    uint32_t aH = aBase + (uint32_t)kt * 512u;
                    uint32_t bH = bBase + (uint32_t)kt * 512u;
                    uint32_t ah[4], al[4], bh[4], bl[4];
                    ldsm4 (ah, aH);
                    ldsm4 (al, aH + 98304u);
                    ldsm4t(bh, bH);
                    ldsm4t(bl, bH + 12288u);
                    float* A0 = (i & 1) ? a0o : a0e;
                    float* A1 = (i & 1) ? a1o : a1e;
                    mma16816(A0, ah, bh);  mma16816(A1, ah, bh + 2);
                    mma16816(A0, ah, bl);  mma16816(A1, ah, bl + 2);
                    mma16816(A0, al, bh);  mma16816(A1, al, bh + 2);
                }
            }
            // x(s+1) prefetch
            float4 rx;
            if (s + 1 < S_LEN) {
                const int tn = dir ? (S_LEN - 2 - s) : (s + 1);
                rx = __ldg((const float4*)(x + (size_t)xk * (S_LEN * 128)
                                             + (size_t)tn * 128 + b_base + xj * 4));
            }
            // C2: wait h(s-1) tiles
            if (s > 0) bar_sync_n(1, 640);
            // C3: h-part GEMM, 8 kts
            {
                int kt = 8 + whalf;
#pragma unroll
                for (int i = 0; i < 8; ++i, kt += 2) {
                    uint32_t aH = aBase + (uint32_t)kt * 512u;
                    uint32_t bH = bBase + (uint32_t)kt * 512u;
                    uint32_t ah[4], al[4], bh[4], bl[4];
                    ldsm4 (ah, aH);
                    ldsm4 (al, aH + 98304u);
                    ldsm4t(bh, bH);
                    ldsm4t(bl, bH + 12288u);
                    float* A0 = (i & 1) ? a0o : a0e;
                    float* A1 = (i & 1) ? a1o : a1e;
                    mma16816(A0, ah, bh);  mma16816(A1, ah, bh + 2);
                    mma16816(A0, ah, bl);  mma16816(A1, ah, bl + 2);
                    mma16816(A0, al, bh);  mma16816(A1, al, bh + 2);
                }
            }
            // C3b: h tiles consumed
            bar_arrive_n(4, 640);
            // C4: x STS + z reduce
            if (s + 1 < S_LEN) {
                uint2 lo, hi = split_pack4(rx, lo);
                *(uint2*)(smem + B_HI_OFF + xfill_off) = hi;
                *(uint2*)(smem + B_LO_OFF + xfill_off) = lo;
            }
            if (whalf) {
                *(float2*)(z_s + r1 * 16 + n0)     = make_float2(a0e[0] + a0o[0], a0e[1] + a0o[1]);
                *(float2*)(z_s + r2 * 16 + n0)     = make_float2(a0e[2] + a0o[2], a0e[3] + a0o[3]);
                *(float2*)(z_s + r1 * 16 + n0 + 8) = make_float2(a1e[0] + a1o[0], a1e[1] + a1o[1]);
                *(float2*)(z_s + r2 * 16 + n0 + 8) = make_float2(a1e[2] + a1o[2], a1e[3] + a1o[3]);
            }
            bar_sync_n(2, 512);
            if (!whalf) {
                float2 p0 = *(float2*)(z_s + r1 * 16 + n0);
                float2 p1 = *(float2*)(z_s + r2 * 16 + n0);
                float2 p2 = *(float2*)(z_s + r1 * 16 + n0 + 8);
                float2 p3 = *(float2*)(z_s + r2 * 16 + n0 + 8);
                *(float2*)(z_s + r1 * 16 + n0)     = make_float2(p0.x + a0e[0] + a0o[0], p0.y + a0e[1] + a0o[1]);
                *(float2*)(z_s + r2 * 16 + n0)     = make_float2(p1.x + a0e[2] + a0o[2], p1.y + a0e[3] + a0o[3]);
                *(float2*)(z_s + r1 * 16 + n0 + 8) = make_float2(p2.x + a1e[0] + a1o[0], p2.y + a1e[1] + a1o[1]);
                *(float2*)(z_s + r2 * 16 + n0 + 8) = make_float2(p3.x + a1e[2] + a1o[2], p3.y + a1e[3] + a1o[3]);
            }
            bar_arrive_n(3, 640);   // z ready for state warps
        }
    } else {
        // ================= STATE WARPS =================
        const int tid2 = tid - 512;          // 0..127
        const int sq   = wid - 16;           // 0..3
        const int cb   = tid2 & 15;
        const int hh0  = (tid2 >> 4) << 2;   // 0,4,...,28
        const int fidx = dir * 64 + btl * 8 + rs;
        const unsigned* fl0 = &g_flag[dir * 64 + btl * 8 + 2 * sq];
        const unsigned* fl1 = fl0 + 1;

        float bF[4], bI[4], bC[4], bO[4], cst[4];
#pragma unroll
        for (int i = 0; i < 4; ++i) {
            bF[i] = bia[0 * 256 + rs * 32 + hh0 + i];
            bI[i] = bia[1 * 256 + rs * 32 + hh0 + i];
            bC[i] = bia[2 * 256 + rs * 32 + hh0 + i];
            bO[i] = bia[3 * 256 + rs * 32 + hh0 + i];
            cst[i] = 0.0f;
        }

        for (int s = 0; s < S_LEN; ++s) {
            const int t = dir ? (S_LEN - 1 - s) : s;
            bar_sync_n(3, 640);              // z(s) ready

            float hv[4];
#pragma unroll
            for (int i = 0; i < 4; ++i) {
                int hh = hh0 + i;
                float zf = z_s[(0   + hh) * 16 + cb] + bF[i];
                float zi = z_s[(32  + hh) * 16 + cb] + bI[i];
                float zc = z_s[(64  + hh) * 16 + cb] + bC[i];
                float zo = z_s[(96  + hh) * 16 + cb] + bO[i];
                cst[i] = sigmoidf_fast(zf) * cst[i] + sigmoidf_fast(zi) * tanhf_fast(zc);
                hv[i]  = sigmoidf_fast(zo) * tanhf_fast(cst[i]);
            }

            if (s + 1 < S_LEN) {
                unsigned char* dst = &g_hx[s & 1][dir][btl][rs][0];
#pragma unroll
                for (int i = 0; i < 4; ++i) {
                    int hh = hh0 + i;
                    uint32_t off = (uint32_t)(((hh >> 3) * 2 + (cb >> 3)) * 128
                                 + (hh & 7) * 16 + (cb & 7) * 2);
                    __nv_bfloat16 h0 = __float2bfloat16_rn(hv[i]);
                    __nv_bfloat16 l0 = __float2bfloat16_rn(hv[i] - __bfloat162float(h0));
                    *(unsigned short*)(dst + off)        = __bfloat16_as_ushort(h0);
                    *(unsigned short*)(dst + 1024 + off) = __bfloat16_as_ushort(l0);
                }
                __syncwarp();
                if (lane == 0) red_release_gpu(&g_flag[fidx], 1u);
            }

            // outputs
            const int b_glob = b_base + cb;
            const int h_glob = rs * 32 + hh0;
            *(float4*)(out + ((size_t)b_glob * S_LEN + t) * 512 + dir * 256 + h_glob)
                = make_float4(hv[0], hv[1], hv[2], hv[3]);
            if (s == S_LEN - 1) {
                size_t base = (size_t)128 * S_LEN * 512;
                size_t off  = ((size_t)dir * 128 + b_glob) * 256 + h_glob;
                *(float4*)(out + base + off) = make_float4(hv[0], hv[1], hv[2], hv[3]);
                *(float4*)(out + base + 2u * 128 * 256 + off)
                    = make_float4(cst[0], cst[1], cst[2], cst[3]);
            }

            if (s + 1 < S_LEN) {
                // poll + LDG 2 slices into regs
                const unsigned tgt = 4u * (unsigned)(s + 1);
                uint4 v[8];
                const unsigned char* s0 = &g_hx[s & 1][dir][btl][2 * sq][0];
                const unsigned char* s1 = &g_hx[s & 1][dir][btl][2 * sq + 1][0];
                while (ld_acquire_gpu(fl0) < tgt) {}
#pragma unroll
                for (int i = 0; i < 4; ++i)
                    v[i] = __ldcg((const uint4*)s0 + lane + 32 * i);
                while (ld_acquire_gpu(fl1) < tgt) {}
#pragma unroll
                for (int i = 0; i < 4; ++i)
                    v[4 + i] = __ldcg((const uint4*)s1 + lane + 32 * i);

                bar_sync_n(4, 640);          // compute done reading h(s-1)
#pragma unroll
                for (int sl = 0; sl < 2; ++sl) {
                    int p = 2 * sq + sl;
#pragma unroll
                    for (int i = 0; i < 4; ++i) {
                        uint32_t boff = (uint32_t)((lane + 32 * i) * 16);
                        char* d = (boff < 1024)
                            ? (smem + B_HI_OFF + 4096 + p * 1024 + boff)
                            : (smem + B_LO_OFF + 4096 + p * 1024 + (boff - 1024));
                        *(uint4*)d = v[sl * 4 + i];
                    }
                }
                bar_arrive_n(1, 640);        // h(s) tiles ready
            }
        }
    }
}

extern "C" void kernel_launch(void* const* d_in, const int* in_sizes, int n_in,
                              void* d_out, int out_size) {
    const float* x  = (const float*)d_in[0];
    const float* Wf = (const float*)d_in[1];
    const float* bf = (const float*)d_in[2];
    const float* Wb = (const float*)d_in[3];
    const float* bb = (const float*)d_in[4];
    float* out = (float*)d_out;

    cudaFuncSetAttribute(bilstm_mma_kernel,
                         cudaFuncAttributeMaxDynamicSharedMemorySize,
                         SMEM_BYTES);

    reset_flag_kernel<<<1, 128>>>();
    bilstm_mma_kernel<<<128, NTHR, SMEM_BYTES>>>(x, Wf, bf, Wb, bb, out);
}